// round 4
// baseline (speedup 1.0000x reference)
#include <cuda_runtime.h>
#include <math.h>

#define NTIME  256
#define NBATCH 8192
#define NHIST  6
#define NSIZE  8

__global__ __launch_bounds__(32) void integrate_kernel(
    const float* __restrict__ times,
    const float* __restrict__ strains,
    const float* __restrict__ temps,
    const float* __restrict__ Ep,
    const float* __restrict__ np_,
    const float* __restrict__ etap,
    const float* __restrict__ s0p,
    const float* __restrict__ Cp,
    const float* __restrict__ gp,
    const float* __restrict__ dcp,
    float* __restrict__ out)
{
    int b = blockIdx.x * blockDim.x + threadIdx.x;
    if (b >= NBATCH) return;

    const float E      = Ep[0];
    const float n      = np_[0];
    const float eta    = etap[0];
    const float s0     = s0p[0];
    const float dcoef  = dcp[0];
    float C[NHIST], G[NHIST];
#pragma unroll
    for (int i = 0; i < NHIST; i++) { C[i] = Cp[i]; G[i] = gp[i]; }
    const float inv_eta = 1.0f / eta;
    const float inv_s0  = 1.0f / s0;
    const bool  n_is_5  = (n == 5.0f);

    // state y = [s, h0..h5, d], init zeros (D0 = 0)
    float s = 0.0f, d = 0.0f;
    float h[NHIST];
#pragma unroll
    for (int i = 0; i < NHIST; i++) h[i] = 0.0f;
    // previous-step state for Newton warm-start extrapolation
    float sP = 0.0f, dP = 0.0f;
    float hP[NHIST];
#pragma unroll
    for (int i = 0; i < NHIST; i++) hP[i] = 0.0f;

    // row 0 of output = init
    {
        float4 z = make_float4(0.f, 0.f, 0.f, 0.f);
        float4* o = (float4*)(out + (size_t)b * NSIZE);
        o[0] = z; o[1] = z;
    }

    float t_prev = times[b];
    float e_prev = strains[b];
    // preload step-1 node values (software pipeline)
    float t_cur = times[NBATCH + b];
    float e_cur = strains[NBATCH + b];
    float T_cur = temps[NBATCH + b];

    for (int t = 1; t < NTIME; t++) {
        // prefetch next step's node data early so DRAM latency hides under Newton
        int tn = (t + 1 < NTIME) ? (t + 1) : t;
        float t_nxt = times[(size_t)tn * NBATCH + b];
        float e_nxt = strains[(size_t)tn * NBATCH + b];
        float T_nxt = temps[(size_t)tn * NBATCH + b];

        float dt = t_cur - t_prev;
        float er = (e_cur - e_prev) / dt;
        // jnp.nan_to_num semantics
        if (!isfinite(er)) er = isnan(er) ? 0.0f : copysignf(3.4028234663852886e38f, er);
        // |fr| = (|over|/s0)^n * exp(-T/1000)/eta = x^n * kk
        float kk  = __expf(-T_cur * 0.001f) * inv_eta;
        float akk = 5.0f * kk * inv_s0;      // derivative constant for n==5

        // step-invariant products (hoisted from the Newton loop)
        float dtE   = dt * E;
        float dtdc  = dt * dcoef;
        float dtEer = dtE * er;
        float dtC[NHIST], dtG[NHIST];
#pragma unroll
        for (int i = 0; i < NHIST; i++) { dtC[i] = dt * C[i]; dtG[i] = dt * G[i]; }

        // Newton warm start: linear extrapolation from the last two states.
        // Same fixed point (R(y*)=0 is independent of the start), fewer iters.
        float ys = s + (s - sP);
        float yd = d + (d - dP);
        float yh[NHIST];
#pragma unroll
        for (int i = 0; i < NHIST; i++) yh[i] = h[i] + (h[i] - hP[i]);

#pragma unroll 1
        for (int it = 0; it < 8; it++) {
            float sumh = ((yh[0] + yh[1]) + (yh[2] + yh[3])) + (yh[4] + yh[5]);
            float over = fmaf(ys, 1.0f - yd, -sumh);
            float x = fabsf(over) * inv_s0;

            float p, alpha;
            if (n_is_5) {
                float x2 = x * x;
                float x4 = x2 * x2;
                p = x4 * x;                         // x^5
                alpha = akk * x4;                   // d|fr|/d|over| -- division free
            } else {
                p = __powf(x, n);
                alpha = (x > 0.0f) ? n * kk * inv_s0 * __fdividef(p, x) : 0.0f;
            }
            float frabs = p * kk;
            float fr    = copysignf(frabs, over);
            float beta  = copysignf(alpha, over);   // d|fr|/dover
            if (over == 0.0f) { fr = 0.0f; beta = 0.0f; }

            // residual R = ynext - y - dt * f(ynext)
            float R0 = (ys - s) - dtEer + dtE * fr;
            float R7 = (yd - d) - dtdc * frabs;
            float Rh[NHIST];
#pragma unroll
            for (int i = 0; i < NHIST; i++)
                Rh[i] = (yh[i] - h[i]) - fmaf(dtC[i], fr, -dtG[i] * yh[i] * frabs);

            // A = I - dt*J = M - dt * u w^T  (M diagonal; rank-1 Sherman-Morrison)
            float u0 = -E * alpha;
            float u7 = dcoef * beta;
            float w0 = 1.0f - yd;
            float w7 = -ys;

            float vi[NHIST], zi[NHIST];
#pragma unroll
            for (int i = 0; i < NHIST; i++) {
                float ui   = fmaf(C[i], alpha, -G[i] * yh[i] * beta);
                float minv = __fdividef(1.0f, fmaf(dtG[i], frabs, 1.0f));
                vi[i] = minv * ui;
                zi[i] = minv * Rh[i];
            }
            // balanced-tree dot products (critical path into rcp(denom))
            float sv = ((vi[0] + vi[1]) + (vi[2] + vi[3])) + (vi[4] + vi[5]);
            float sz = ((zi[0] + zi[1]) + (zi[2] + zi[3])) + (zi[4] + zi[5]);
            float wv = fmaf(w0, u0, w7 * u7) - sv;  // w^T M^-1 u  (w_i = -1)
            float wz = fmaf(w0, R0, w7 * R7) - sz;  // w^T M^-1 R

            float denom = fmaf(-dt, wv, 1.0f);
            float cfac  = dt * __fdividef(wz, denom);

            // dx = M^-1 R + cfac * M^-1 u ; y -= dx
            float dx0 = fmaf(cfac, u0, R0);
            float dx7 = fmaf(cfac, u7, R7);
            float dxi[NHIST];
#pragma unroll
            for (int i = 0; i < NHIST; i++) dxi[i] = fmaf(cfac, vi[i], zi[i]);

            ys -= dx0;
            yd -= dx7;
#pragma unroll
            for (int i = 0; i < NHIST; i++) yh[i] -= dxi[i];

            // convergence metrics as balanced trees (gates next iteration)
            float adx = ((fabsf(dx0)    + fabsf(dx7))    +
                         (fabsf(dxi[0]) + fabsf(dxi[1]))) +
                        ((fabsf(dxi[2]) + fabsf(dxi[3])) +
                         (fabsf(dxi[4]) + fabsf(dxi[5])));
            float ay  = ((fabsf(ys) + 1.0f) + (fabsf(yh[0]) + fabsf(yh[1]))) +
                        ((fabsf(yh[2]) + fabsf(yh[3])) + (fabsf(yh[4]) + fabsf(yh[5])));
            // tight early exit: only once fully converged (safe vs 8 fixed iters)
            if (adx <= 1e-6f * ay) break;
        }

        sP = s; dP = d;
#pragma unroll
        for (int i = 0; i < NHIST; i++) hP[i] = h[i];
        s = ys; d = yd;
#pragma unroll
        for (int i = 0; i < NHIST; i++) h[i] = yh[i];

        float4* o = (float4*)(out + ((size_t)t * NBATCH + (size_t)b) * NSIZE);
        o[0] = make_float4(s, h[0], h[1], h[2]);
        o[1] = make_float4(h[3], h[4], h[5], d);

        t_prev = t_cur; e_prev = e_cur;
        t_cur = t_nxt;  e_cur = e_nxt;  T_cur = T_nxt;
    }
}

extern "C" void kernel_launch(void* const* d_in, const int* in_sizes, int n_in,
                              void* d_out, int out_size)
{
    (void)in_sizes; (void)n_in; (void)out_size;
    const float* times   = (const float*)d_in[0];
    const float* strains = (const float*)d_in[1];
    const float* temps   = (const float*)d_in[2];
    const float* E       = (const float*)d_in[3];
    const float* n       = (const float*)d_in[4];
    const float* eta     = (const float*)d_in[5];
    const float* s0      = (const float*)d_in[6];
    const float* C       = (const float*)d_in[7];
    const float* g       = (const float*)d_in[8];
    const float* dcoef   = (const float*)d_in[9];
    float* out = (float*)d_out;

    integrate_kernel<<<(NBATCH + 31) / 32, 32>>>(
        times, strains, temps, E, n, eta, s0, C, g, dcoef, out);
}

// round 11
// speedup vs baseline: 1.0815x; 1.0815x over previous
#include <cuda_runtime.h>
#include <math.h>

#define NTIME  256
#define NBATCH 8192
#define NHIST  6
#define NSIZE  8

typedef unsigned long long u64;

// ---- packed f32x2 helpers (sm_100+ PTX; one SASS op for two floats) ----
#define F2PACK(dst, lo, hi) \
    asm("mov.b64 %0, {%1, %2};" : "=l"(dst) : "r"(__float_as_uint(lo)), "r"(__float_as_uint(hi)))
#define F2UNPACK(lo, hi, src) do { unsigned _ulo, _uhi; \
    asm("mov.b64 {%0, %1}, %2;" : "=r"(_ulo), "=r"(_uhi) : "l"(src)); \
    (lo) = __uint_as_float(_ulo); (hi) = __uint_as_float(_uhi); } while (0)
#define F2ADD(d, a, b) asm("add.rn.f32x2 %0, %1, %2;" : "=l"(d) : "l"(a), "l"(b))
#define F2MUL(d, a, b) asm("mul.rn.f32x2 %0, %1, %2;" : "=l"(d) : "l"(a), "l"(b))
#define F2FMA(d, a, b, c) asm("fma.rn.f32x2 %0, %1, %2, %3;" : "=l"(d) : "l"(a), "l"(b), "l"(c))

#define SIGNMASK2 0x8000000080000000ULL
#define ABSMASK2  0x7FFFFFFF7FFFFFFFULL
#define NPAIR (NHIST / 2)

__global__ __launch_bounds__(32) void integrate_kernel(
    const float* __restrict__ times,
    const float* __restrict__ strains,
    const float* __restrict__ temps,
    const float* __restrict__ Ep,
    const float* __restrict__ np_,
    const float* __restrict__ etap,
    const float* __restrict__ s0p,
    const float* __restrict__ Cp,
    const float* __restrict__ gp,
    const float* __restrict__ dcp,
    float* __restrict__ out)
{
    int b = blockIdx.x * blockDim.x + threadIdx.x;
    if (b >= NBATCH) return;

    const float E      = Ep[0];
    const float n      = np_[0];
    const float eta    = etap[0];
    const float s0     = s0p[0];
    const float dcoef  = dcp[0];
    const float inv_eta = 1.0f / eta;
    const float inv_s0  = 1.0f / s0;
    const bool  n_is_5  = (n == 5.0f);

    float Cs[NHIST], Gs[NHIST];
#pragma unroll
    for (int i = 0; i < NHIST; i++) { Cs[i] = Cp[i]; Gs[i] = gp[i]; }

    // material-constant pairs (invariant for whole kernel)
    u64 Cpk[NPAIR], Gpk[NPAIR], nCpk[NPAIR];
#pragma unroll
    for (int i = 0; i < NPAIR; i++) {
        F2PACK(Cpk[i], Cs[2*i], Cs[2*i+1]);
        F2PACK(Gpk[i], Gs[2*i], Gs[2*i+1]);
        nCpk[i] = Cpk[i] ^ SIGNMASK2;
    }
    u64 one2, none2;
    F2PACK(one2, 1.0f, 1.0f);
    F2PACK(none2, -1.0f, -1.0f);

    // state: s, d scalar; histories as 3 packed pairs. all zero (D0 = 0)
    float s = 0.0f, d = 0.0f;
    float sP = 0.0f, dP = 0.0f;
    u64 hpk[NPAIR], hPpk[NPAIR];
#pragma unroll
    for (int i = 0; i < NPAIR; i++) { hpk[i] = 0ULL; hPpk[i] = 0ULL; }

    // row 0 of output = init
    {
        float4 z = make_float4(0.f, 0.f, 0.f, 0.f);
        float4* o = (float4*)(out + (size_t)b * NSIZE);
        o[0] = z; o[1] = z;
    }

    float t_prev = times[b];
    float e_prev = strains[b];
    float t_cur = times[NBATCH + b];
    float e_cur = strains[NBATCH + b];
    float T_cur = temps[NBATCH + b];

    for (int t = 1; t < NTIME; t++) {
        // prefetch next step's node data (hides DRAM latency under Newton)
        int tn = (t + 1 < NTIME) ? (t + 1) : t;
        float t_nxt = times[(size_t)tn * NBATCH + b];
        float e_nxt = strains[(size_t)tn * NBATCH + b];
        float T_nxt = temps[(size_t)tn * NBATCH + b];

        float dt = t_cur - t_prev;
        float er = (e_cur - e_prev) / dt;
        if (!isfinite(er)) er = isnan(er) ? 0.0f : copysignf(3.4028234663852886e38f, er);
        // |fr| = (|over|/s0)^n * exp(-T/1000)/eta = x^n * kk
        float kk  = __expf(-T_cur * 0.001f) * inv_eta;
        float akk = 5.0f * kk * inv_s0;          // derivative const for n==5

        // step-invariant scalars + packed products
        float dtE   = dt * E;
        float dtdc  = dt * dcoef;
        float dtEer = dtE * er;
        u64 dt2;
        F2PACK(dt2, dt, dt);
        u64 dtGpk[NPAIR], ndtCpk[NPAIR], nhpk[NPAIR];
#pragma unroll
        for (int i = 0; i < NPAIR; i++) {
            F2MUL(dtGpk[i], Gpk[i], dt2);        // dt*G pair
            F2MUL(ndtCpk[i], nCpk[i], dt2);      // -dt*C pair
            nhpk[i] = hpk[i] ^ SIGNMASK2;        // -h pair
        }

        // per-step convergence tolerance
        float tol = 1e-5f * (fabsf(s) + 1.0f);

        // Newton warm start: y = h + (h - hP) (same fixed point, fewer iters)
        float ys = s + (s - sP);
        float yd = d + (d - dP);
        u64 yhpk[NPAIR];
#pragma unroll
        for (int i = 0; i < NPAIR; i++) {
            u64 diff;
            F2FMA(diff, hPpk[i], none2, hpk[i]); // h - hP
            F2ADD(yhpk[i], hpk[i], diff);
        }

#pragma unroll 1
        for (int it = 0; it < 8; it++) {
            // sum of histories (packed tree)
            u64 t1, t2;
            F2ADD(t1, yhpk[0], yhpk[1]);
            F2ADD(t2, t1, yhpk[2]);
            float sa, sb;
            F2UNPACK(sa, sb, t2);
            float sumh = sa + sb;

            float over = fmaf(ys, 1.0f - yd, -sumh);
            float x = fabsf(over) * inv_s0;

            float p, alpha;
            if (n_is_5) {
                float x2 = x * x;
                float x4 = x2 * x2;
                p = x4 * x;                      // x^5
                alpha = akk * x4;                // d|fr|/d|over|, division-free
            } else {
                p = __powf(x, n);
                alpha = (x > 0.0f) ? n * kk * inv_s0 * __fdividef(p, x) : 0.0f;
            }
            float frabs = p * kk;
            float fr    = copysignf(frabs, over);
            float beta  = copysignf(alpha, over);

            // scalar rows (stress, damage)
            float R0 = (ys - s) - dtEer + dtE * fr;
            float R7 = (yd - d) - dtdc * frabs;
            float u0 = -E * alpha;
            float u7 = dcoef * beta;
            float w0 = 1.0f - yd;
            float w7 = -ys;

            // broadcasts
            u64 fr2, frabs2, alpha2, nbeta2;
            F2PACK(fr2, fr, fr);
            F2PACK(frabs2, frabs, frabs);
            F2PACK(alpha2, alpha, alpha);
            F2PACK(nbeta2, -beta, -beta);

            // packed history rows: residual, u, M^-1 apply
            u64 vpk[NPAIR], zpk[NPAIR];
#pragma unroll
            for (int i = 0; i < NPAIR; i++) {
                u64 d0, d1, gy, gydt, Rh, tq, ui, den, minv;
                F2ADD(d0, yhpk[i], nhpk[i]);              // yh - h
                F2FMA(d1, ndtCpk[i], fr2, d0);            //  - dtC*fr
                F2MUL(gy, Gpk[i], yhpk[i]);               // G*yh
                F2MUL(gydt, gy, dt2);                     // dtG*yh
                F2FMA(Rh, gydt, frabs2, d1);              // R_h
                F2MUL(tq, gy, nbeta2);                    // -G*yh*beta
                F2FMA(ui, Cpk[i], alpha2, tq);            // u_h
                F2FMA(den, dtGpk[i], frabs2, one2);       // 1 + dtG*frabs
                float dl, dh;
                F2UNPACK(dl, dh, den);
                float ml = __fdividef(1.0f, dl);
                float mh = __fdividef(1.0f, dh);
                F2PACK(minv, ml, mh);
                F2MUL(vpk[i], minv, ui);                  // M^-1 u
                F2MUL(zpk[i], minv, Rh);                  // M^-1 R
            }

            // Sherman-Morrison dots (w_i = -1 on history comps)
            u64 svp, szp;
            F2ADD(svp, vpk[0], vpk[1]);  F2ADD(svp, svp, vpk[2]);
            F2ADD(szp, zpk[0], zpk[1]);  F2ADD(szp, szp, zpk[2]);
            float svl, svh, szl, szh;
            F2UNPACK(svl, svh, svp);
            F2UNPACK(szl, szh, szp);
            float wv = fmaf(w0, u0, w7 * u7) - (svl + svh);
            float wz = fmaf(w0, R0, w7 * R7) - (szl + szh);

            float denom = fmaf(-dt, wv, 1.0f);
            float cfac  = dt * __fdividef(wz, denom);
            u64 cfac2;
            F2PACK(cfac2, cfac, cfac);

            // updates
            float dx0 = fmaf(cfac, u0, R0);
            float dx7 = fmaf(cfac, u7, R7);
            ys -= dx0;
            yd -= dx7;
            u64 adp;
            {
                u64 dxp0, dxp1, dxp2, aa, ab2;
                F2FMA(dxp0, cfac2, vpk[0], zpk[0]);
                F2FMA(dxp1, cfac2, vpk[1], zpk[1]);
                F2FMA(dxp2, cfac2, vpk[2], zpk[2]);
                F2FMA(yhpk[0], dxp0, none2, yhpk[0]);     // yh -= dx
                F2FMA(yhpk[1], dxp1, none2, yhpk[1]);
                F2FMA(yhpk[2], dxp2, none2, yhpk[2]);
                aa  = (dxp0 & ABSMASK2);
                ab2 = (dxp1 & ABSMASK2);
                F2ADD(aa, aa, ab2);
                ab2 = (dxp2 & ABSMASK2);
                F2ADD(adp, aa, ab2);
            }
            float al, ah;
            F2UNPACK(al, ah, adp);
            float adx = (fabsf(dx0) + fabsf(dx7)) + (al + ah);

            // warp-uniform exit (warp runs max(lane iters) regardless)
            if (__all_sync(0xFFFFFFFFu, adx <= tol)) break;
        }

        sP = s; dP = d;
        s = ys; d = yd;
#pragma unroll
        for (int i = 0; i < NPAIR; i++) { hPpk[i] = hpk[i]; hpk[i] = yhpk[i]; }

        float h0, h1, h2, h3, h4, h5;
        F2UNPACK(h0, h1, hpk[0]);
        F2UNPACK(h2, h3, hpk[1]);
        F2UNPACK(h4, h5, hpk[2]);
        float4* o = (float4*)(out + ((size_t)t * NBATCH + (size_t)b) * NSIZE);
        o[0] = make_float4(s, h0, h1, h2);
        o[1] = make_float4(h3, h4, h5, d);

        t_prev = t_cur; e_prev = e_cur;
        t_cur = t_nxt;  e_cur = e_nxt;  T_cur = T_nxt;
    }
}

extern "C" void kernel_launch(void* const* d_in, const int* in_sizes, int n_in,
                              void* d_out, int out_size)
{
    (void)in_sizes; (void)n_in; (void)out_size;
    const float* times   = (const float*)d_in[0];
    const float* strains = (const float*)d_in[1];
    const float* temps   = (const float*)d_in[2];
    const float* E       = (const float*)d_in[3];
    const float* n       = (const float*)d_in[4];
    const float* eta     = (const float*)d_in[5];
    const float* s0      = (const float*)d_in[6];
    const float* C       = (const float*)d_in[7];
    const float* g       = (const float*)d_in[8];
    const float* dcoef   = (const float*)d_in[9];
    float* out = (float*)d_out;

    integrate_kernel<<<NBATCH / 32, 32>>>(
        times, strains, temps, E, n, eta, s0, C, g, dcoef, out);
}

// round 13
// speedup vs baseline: 1.2438x; 1.1501x over previous
#include <cuda_runtime.h>
#include <math.h>

#define NTIME  256
#define NBATCH 8192
#define NHIST  6
#define NSIZE  8
#define NPAIR  3

typedef unsigned long long u64;

// ---- packed f32x2 helpers (sm_100+; one SASS op for two floats) ----
#define F2PACK(dst, lo, hi) \
    asm("mov.b64 %0, {%1, %2};" : "=l"(dst) : "r"(__float_as_uint(lo)), "r"(__float_as_uint(hi)))
#define F2UNPACK(lo, hi, src) do { unsigned _ulo, _uhi; \
    asm("mov.b64 {%0, %1}, %2;" : "=r"(_ulo), "=r"(_uhi) : "l"(src)); \
    (lo) = __uint_as_float(_ulo); (hi) = __uint_as_float(_uhi); } while (0)
#define F2ADD(d, a, b) asm("add.rn.f32x2 %0, %1, %2;" : "=l"(d) : "l"(a), "l"(b))
#define F2MUL(d, a, b) asm("mul.rn.f32x2 %0, %1, %2;" : "=l"(d) : "l"(a), "l"(b))
#define F2FMA(d, a, b, c) asm("fma.rn.f32x2 %0, %1, %2, %3;" : "=l"(d) : "l"(a), "l"(b), "l"(c))

__global__ __launch_bounds__(32) void integrate_kernel(
    const float* __restrict__ times,
    const float* __restrict__ strains,
    const float* __restrict__ temps,
    const float* __restrict__ Ep,
    const float* __restrict__ np_,
    const float* __restrict__ etap,
    const float* __restrict__ s0p,
    const float* __restrict__ Cp,
    const float* __restrict__ gp,
    const float* __restrict__ dcp,
    float* __restrict__ out)
{
    int b = blockIdx.x * blockDim.x + threadIdx.x;
    if (b >= NBATCH) return;

    const float E      = Ep[0];
    const float n      = np_[0];
    const float eta    = etap[0];
    const float s0     = s0p[0];
    const float dcoef  = dcp[0];
    const float inv_eta = 1.0f / eta;
    const float inv_s0  = 1.0f / s0;
    const bool  n_is_5  = (n == 5.0f);

    // material-constant pairs
    u64 Cpk[NPAIR], Gpk[NPAIR];
#pragma unroll
    for (int i = 0; i < NPAIR; i++) {
        F2PACK(Cpk[i], Cp[2*i], Cp[2*i+1]);
        F2PACK(Gpk[i], gp[2*i], gp[2*i+1]);
    }
    u64 one2, none2, two2;
    F2PACK(one2,  1.0f, 1.0f);
    F2PACK(none2, -1.0f, -1.0f);
    F2PACK(two2,  2.0f, 2.0f);

    // state: s, d scalar; histories packed. all zero (D0 = 0)
    float s = 0.0f, d = 0.0f;
    u64 hpk[NPAIR];
#pragma unroll
    for (int i = 0; i < NPAIR; i++) hpk[i] = 0ULL;
    // previous overstress values for scalar-Newton warm start
    float ov = 0.0f, ovP = 0.0f;

    // row 0 of output = init
    {
        float4 z = make_float4(0.f, 0.f, 0.f, 0.f);
        float4* o = (float4*)(out + (size_t)b * NSIZE);
        o[0] = z; o[1] = z;
    }

    float t_prev = times[b];
    float e_prev = strains[b];
    float t_cur = times[NBATCH + b];
    float e_cur = strains[NBATCH + b];
    float T_cur = temps[NBATCH + b];

    for (int t = 1; t < NTIME; t++) {
        // prefetch next step's node data (hides DRAM latency under Newton)
        int tn = (t + 1 < NTIME) ? (t + 1) : t;
        float t_nxt = times[(size_t)tn * NBATCH + b];
        float e_nxt = strains[(size_t)tn * NBATCH + b];
        float T_nxt = temps[(size_t)tn * NBATCH + b];

        float dt = t_cur - t_prev;
        float er = (e_cur - e_prev) / dt;
        if (!isfinite(er)) er = isnan(er) ? 0.0f : copysignf(3.4028234663852886e38f, er);
        // |fr| = (|over|/s0)^n * exp(-T/1000)/eta = x^n * kk
        float kk  = __expf(-T_cur * 0.001f) * inv_eta;
        float akk = 5.0f * kk * inv_s0;

        float dtE    = dt * E;
        float dtdc   = dt * dcoef;
        float s_pred = fmaf(dtE, er, s);     // elastic predictor
        u64 dt2;
        F2PACK(dt2, dt, dt);
        u64 dtG2[NPAIR], dtC2[NPAIR];
#pragma unroll
        for (int i = 0; i < NPAIR; i++) {
            F2MUL(dtG2[i], Gpk[i], dt2);
            F2MUL(dtC2[i], Cpk[i], dt2);
        }

        // residual tolerance in over-units (state sensitivity ~ O(1))
        float tol = 1e-6f * (fabsf(s) + s0);

        // warm start: linear extrapolation of the converged overstress
        float over = ov + (ov - ovP);

        float s1 = s_pred, d1 = d;
        u64 hp[NPAIR], rinv[NPAIR];
        float frabs, x, x4s, p;

        // scalar Newton on g(over) = over - s'(1-d') + sum h'  == 0
        for (int it = 0; ; ++it) {
            x = fabsf(over) * inv_s0;
            if (n_is_5) {
                float x2 = x * x;
                x4s = x2 * x2;
                p = x4s * x;                       // x^5
            } else {
                p = __powf(x, n);
                x4s = 0.0f;
            }
            frabs = p * kk;
            float fr = copysignf(frabs, over);
            s1 = fmaf(-dtE, fr, s_pred);           // s'
            d1 = fmaf(dtdc, frabs, d);             // d'
            u64 fr2, frabs2;
            F2PACK(fr2, fr, fr);
            F2PACK(frabs2, frabs, frabs);

            // h'_i = (h_i + dtC_i*fr) / (1 + dtG_i*|fr|), rcp by 1-step NR (eps tiny)
#pragma unroll
            for (int i = 0; i < NPAIR; i++) {
                u64 eps, num, y0, nD, tt;
                F2MUL(eps, dtG2[i], frabs2);       // eps = dtG*|fr|
                F2FMA(num, dtC2[i], fr2, hpk[i]);  // h + dtC*fr
                F2FMA(y0, eps, none2, one2);       // 1 - eps   (~1/D, err eps^2)
                F2FMA(nD, eps, none2, none2);      // -(1+eps) = -D
                F2FMA(tt, nD, y0, two2);           // 2 - D*y0
                F2MUL(rinv[i], y0, tt);            // 1/D, err eps^4
                F2MUL(hp[i], num, rinv[i]);        // h'
            }
            u64 sh;
            F2ADD(sh, hp[0], hp[1]);
            F2ADD(sh, sh, hp[2]);
            float shl, shh;
            F2UNPACK(shl, shh, sh);
            float g = fmaf(-s1, 1.0f - d1, over) + (shl + shh);

            bool conv = fabsf(g) <= tol;
            if (__all_sync(0xFFFFFFFFu, conv) || it == 8) break;

            // derivative d g / d over
            float alpha, beta;
            if (n_is_5) {
                alpha = akk * x4s;
            } else {
                alpha = (x > 0.0f) ? n * kk * inv_s0 * __fdividef(p, x) : 0.0f;
            }
            beta = copysignf(alpha, over);
            u64 a2, nb2;
            F2PACK(a2, alpha, alpha);
            F2PACK(nb2, -beta, -beta);
            u64 ds;
#pragma unroll
            for (int i = 0; i < NPAIR; i++) {
                u64 q, t2, term, contrib;
                F2MUL(q, hp[i], dtG2[i]);          // h'*dtG
                F2MUL(t2, q, nb2);                 // -h'*dtG*beta
                F2FMA(term, dtC2[i], a2, t2);      // dtC*alpha - h'*dtG*beta
                F2MUL(contrib, term, rinv[i]);     // * 1/D
                if (i == 0) ds = contrib; else F2ADD(ds, ds, contrib);
            }
            float dsl, dsh;
            F2UNPACK(dsl, dsh, ds);
            float gprime = 1.0f + dtE * alpha * (1.0f - d1)
                         + s1 * dtdc * beta + (dsl + dsh);
            over -= __fdividef(g, gprime);
        }

        // commit converged state (s1, d1, hp consistent with final over)
        ovP = ov; ov = over;
        s = s1; d = d1;
#pragma unroll
        for (int i = 0; i < NPAIR; i++) hpk[i] = hp[i];

        float h0, h1, h2, h3, h4, h5;
        F2UNPACK(h0, h1, hpk[0]);
        F2UNPACK(h2, h3, hpk[1]);
        F2UNPACK(h4, h5, hpk[2]);
        float4* o = (float4*)(out + ((size_t)t * NBATCH + (size_t)b) * NSIZE);
        o[0] = make_float4(s, h0, h1, h2);
        o[1] = make_float4(h3, h4, h5, d);

        t_prev = t_cur; e_prev = e_cur;
        t_cur = t_nxt;  e_cur = e_nxt;  T_cur = T_nxt;
    }
}

extern "C" void kernel_launch(void* const* d_in, const int* in_sizes, int n_in,
                              void* d_out, int out_size)
{
    (void)in_sizes; (void)n_in; (void)out_size;
    const float* times   = (const float*)d_in[0];
    const float* strains = (const float*)d_in[1];
    const float* temps   = (const float*)d_in[2];
    const float* E       = (const float*)d_in[3];
    const float* n       = (const float*)d_in[4];
    const float* eta     = (const float*)d_in[5];
    const float* s0      = (const float*)d_in[6];
    const float* C       = (const float*)d_in[7];
    const float* g       = (const float*)d_in[8];
    const float* dcoef   = (const float*)d_in[9];
    float* out = (float*)d_out;

    integrate_kernel<<<NBATCH / 32, 32>>>(
        times, strains, temps, E, n, eta, s0, C, g, dcoef, out);
}

// round 17
// speedup vs baseline: 1.6135x; 1.2973x over previous
#include <cuda_runtime.h>
#include <math.h>

#define NTIME  256
#define NBATCH 8192
#define NHIST  6
#define NSIZE  8
#define NPAIR  3

typedef unsigned long long u64;

// ---- packed f32x2 helpers (sm_100+; one SASS op for two floats) ----
#define F2PACK(dst, lo, hi) \
    asm("mov.b64 %0, {%1, %2};" : "=l"(dst) : "r"(__float_as_uint(lo)), "r"(__float_as_uint(hi)))
#define F2UNPACK(lo, hi, src) do { unsigned _ulo, _uhi; \
    asm("mov.b64 {%0, %1}, %2;" : "=r"(_ulo), "=r"(_uhi) : "l"(src)); \
    (lo) = __uint_as_float(_ulo); (hi) = __uint_as_float(_uhi); } while (0)
#define F2ADD(d, a, b) asm("add.rn.f32x2 %0, %1, %2;" : "=l"(d) : "l"(a), "l"(b))
#define F2MUL(d, a, b) asm("mul.rn.f32x2 %0, %1, %2;" : "=l"(d) : "l"(a), "l"(b))
#define F2FMA(d, a, b, c) asm("fma.rn.f32x2 %0, %1, %2, %3;" : "=l"(d) : "l"(a), "l"(b), "l"(c))

__global__ __launch_bounds__(32) void integrate_kernel(
    const float* __restrict__ times,
    const float* __restrict__ strains,
    const float* __restrict__ temps,
    const float* __restrict__ Ep,
    const float* __restrict__ np_,
    const float* __restrict__ etap,
    const float* __restrict__ s0p,
    const float* __restrict__ Cp,
    const float* __restrict__ gp,
    const float* __restrict__ dcp,
    float* __restrict__ out)
{
    int b = blockIdx.x * blockDim.x + threadIdx.x;
    if (b >= NBATCH) return;

    const float E      = Ep[0];
    const float n      = np_[0];
    const float eta    = etap[0];
    const float s0     = s0p[0];
    const float dcoef  = dcp[0];
    const float inv_eta = 1.0f / eta;
    const float inv_s0  = 1.0f / s0;
    const bool  n_is_5  = (n == 5.0f);

    u64 Cpk[NPAIR], Gpk[NPAIR];
#pragma unroll
    for (int i = 0; i < NPAIR; i++) {
        F2PACK(Cpk[i], Cp[2*i], Cp[2*i+1]);
        F2PACK(Gpk[i], gp[2*i], gp[2*i+1]);
    }
    u64 one2, none2;
    F2PACK(one2,  1.0f, 1.0f);
    F2PACK(none2, -1.0f, -1.0f);

    // state (all zero; D0 = 0)
    float s = 0.0f, d = 0.0f;
    u64 hpk[NPAIR];
#pragma unroll
    for (int i = 0; i < NPAIR; i++) hpk[i] = 0ULL;
    float ov = 0.0f, ovP = 0.0f;   // overstress history for warm start

    // row 0 of output = init
    {
        float4 z = make_float4(0.f, 0.f, 0.f, 0.f);
        float4* o = (float4*)(out + (size_t)b * NSIZE);
        o[0] = z; o[1] = z;
    }

    // node 0 and node 1 data; constants for step 1 (computed up front)
    float t_cur, e_cur;
    float kk, akk, dtE, dtdc, Einc;
    u64 dtG2[NPAIR], dtC2[NPAIR];
    {
        float t0 = times[b],          e0 = strains[b];
        float t1 = times[NBATCH + b], e1 = strains[NBATCH + b];
        float T1 = temps[NBATCH + b];
        float dt = t1 - t0;
        Einc = E * (e1 - e0);        // == dtE * er  (division cancels)
        kk   = __expf(-T1 * 0.001f) * inv_eta;
        akk  = 5.0f * kk * inv_s0;
        dtE  = dt * E;
        dtdc = dt * dcoef;
        u64 dt2; F2PACK(dt2, dt, dt);
#pragma unroll
        for (int i = 0; i < NPAIR; i++) {
            F2MUL(dtG2[i], Gpk[i], dt2);
            F2MUL(dtC2[i], Cpk[i], dt2);
        }
        t_cur = t1; e_cur = e1;
    }

#pragma unroll 1
    for (int t = 1; t < NTIME; t++) {
        // issue loads for node t+1 early (arrive during Newton)
        int tn = (t + 1 < NTIME) ? (t + 1) : t;
        float t_nxt = times[(size_t)tn * NBATCH + b];
        float e_nxt = strains[(size_t)tn * NBATCH + b];
        float T_nxt = temps[(size_t)tn * NBATCH + b];

        float s_pred = s + Einc;                  // elastic predictor
        float tol    = 1e-5f * (fabsf(s) + s0);
        float over   = ov + (ov - ovP);           // warm start

        float s1, d1;
        u64 hp[NPAIR], rinv[NPAIR];

        // scalar Newton on g(over) = over - s'(1-d') + sum h' == 0
#pragma unroll 1
        for (int it = 0; it < 9; ++it) {
            float x  = fabsf(over) * inv_s0;
            float x4s, p;
            if (n_is_5) {
                float x2 = x * x;
                x4s = x2 * x2;
                p   = x4s * x;                    // x^5
            } else {
                p = __powf(x, n);
                x4s = 0.0f;
            }
            float frabs = p * kk;
            float fr    = copysignf(frabs, over);
            s1 = fmaf(-dtE, fr, s_pred);          // s'
            d1 = fmaf(dtdc, frabs, d);            // d'
            u64 fr2, frabs2;
            F2PACK(fr2, fr, fr);
            F2PACK(frabs2, frabs, frabs);

            // h'_i = (h + dtC*fr)/(1 + dtG*|fr|); 1/D ~= 1 - e + e^2 (e tiny)
#pragma unroll
            for (int i = 0; i < NPAIR; i++) {
                u64 eps, num, t1_, r;
                F2MUL(eps, dtG2[i], frabs2);      // e = dtG*|fr|
                F2FMA(num, dtC2[i], fr2, hpk[i]); // h + dtC*fr
                F2FMA(t1_, eps, none2, one2);     // 1 - e
                F2FMA(r, eps, eps, t1_);          // 1 - e + e^2
                rinv[i] = r;
                F2MUL(hp[i], num, r);             // h'
            }
            u64 sh;
            F2ADD(sh, hp[0], hp[1]);
            F2ADD(sh, sh, hp[2]);
            float shl, shh;
            F2UNPACK(shl, shh, sh);
            float g = fmaf(-s1, 1.0f - d1, over) + (shl + shh);

            // derivative (computed unconditionally, in parallel with g tail)
            float alpha = n_is_5 ? (akk * x4s)
                                 : ((x > 0.0f) ? n * kk * inv_s0 * __fdividef(p, x) : 0.0f);
            float beta  = copysignf(alpha, over);
            u64 a2, nb2;
            F2PACK(a2, alpha, alpha);
            F2PACK(nb2, -beta, -beta);
            u64 ds;
#pragma unroll
            for (int i = 0; i < NPAIR; i++) {
                u64 q_, t2_, term, contrib;
                F2MUL(q_, hp[i], dtG2[i]);        // h'*dtG
                F2MUL(t2_, q_, nb2);              // -h'*dtG*beta
                F2FMA(term, dtC2[i], a2, t2_);    // dtC*alpha - h'*dtG*beta
                F2MUL(contrib, term, rinv[i]);
                if (i == 0) ds = contrib; else F2ADD(ds, ds, contrib);
            }
            float dsl, dsh;
            F2UNPACK(dsl, dsh, ds);
            float gprime = 1.0f + dtE * alpha * (1.0f - d1)
                         + s1 * dtdc * beta + (dsl + dsh);

            // divide first; vote/branch resolve in its latency shadow
            float q = __fdividef(g, gprime);
            if (__all_sync(0xFFFFFFFFu, fabsf(g) <= tol)) break;
            over -= q;
        }

        // commit converged state (consistent with final 'over')
        ovP = ov; ov = over;
        s = s1; d = d1;
#pragma unroll
        for (int i = 0; i < NPAIR; i++) hpk[i] = hp[i];

        float h0, h1, h2, h3, h4, h5;
        F2UNPACK(h0, h1, hpk[0]);
        F2UNPACK(h2, h3, hpk[1]);
        F2UNPACK(h4, h5, hpk[2]);
        float4* o = (float4*)(out + ((size_t)t * NBATCH + (size_t)b) * NSIZE);
        o[0] = make_float4(s, h0, h1, h2);
        o[1] = make_float4(h3, h4, h5, d);

        // software-pipelined constants for step t+1 (off the critical chain;
        // uses loads issued at this step's start, long since arrived)
        {
            float dt = t_nxt - t_cur;
            Einc = E * (e_nxt - e_cur);
            kk   = __expf(-T_nxt * 0.001f) * inv_eta;
            akk  = 5.0f * kk * inv_s0;
            dtE  = dt * E;
            dtdc = dt * dcoef;
            u64 dt2; F2PACK(dt2, dt, dt);
#pragma unroll
            for (int i = 0; i < NPAIR; i++) {
                F2MUL(dtG2[i], Gpk[i], dt2);
                F2MUL(dtC2[i], Cpk[i], dt2);
            }
            t_cur = t_nxt; e_cur = e_nxt;
        }
    }
}

extern "C" void kernel_launch(void* const* d_in, const int* in_sizes, int n_in,
                              void* d_out, int out_size)
{
    (void)in_sizes; (void)n_in; (void)out_size;
    const float* times   = (const float*)d_in[0];
    const float* strains = (const float*)d_in[1];
    const float* temps   = (const float*)d_in[2];
    const float* E       = (const float*)d_in[3];
    const float* n       = (const float*)d_in[4];
    const float* eta     = (const float*)d_in[5];
    const float* s0      = (const float*)d_in[6];
    const float* C       = (const float*)d_in[7];
    const float* g       = (const float*)d_in[8];
    const float* dcoef   = (const float*)d_in[9];
    float* out = (float*)d_out;

    integrate_kernel<<<NBATCH / 32, 32>>>(
        times, strains, temps, E, n, eta, s0, C, g, dcoef, out);
}